// round 2
// baseline (speedup 1.0000x reference)
#include <cuda_runtime.h>

// Problem constants (fixed by the dataset)
#define BATCH 8192
#define HDIM  512
#define DPTH  16

// Per-sample partial losses (scratch; __device__ global per allocation rules)
__device__ float g_perword[BATCH];

// One CTA per sample. 512 threads = 16 warps; warp w computes logit for
// huffman path row d = w via a coalesced float4 dot product against the
// smem-staged hidden vector.
__global__ __launch_bounds__(512) void hs_main_kernel(
    const float* __restrict__ hidden,     // [BATCH, HDIM]
    const int*   __restrict__ target,     // [BATCH]
    const float* __restrict__ weights,    // [V, DPTH, HDIM]
    const float* __restrict__ codes,      // [V, DPTH]
    const int*   __restrict__ lengths)    // [V]
{
    const int b    = blockIdx.x;
    const int tid  = threadIdx.x;
    const int warp = tid >> 5;
    const int lane = tid & 31;

    __shared__ float sh[HDIM];
    __shared__ float slog[DPTH];

    const int word = target[b];

    // Stage hidden[b] into shared memory (128 float4 loads, threads 0..127)
    const float4* h4 = reinterpret_cast<const float4*>(hidden + (size_t)b * HDIM);
    if (tid < HDIM / 4) {
        reinterpret_cast<float4*>(sh)[tid] = h4[tid];
    }
    __syncthreads();

    // Dot product: warp `warp` handles weight row d = warp (contiguous 2KB)
    const float4* w4 =
        reinterpret_cast<const float4*>(weights + ((size_t)word * DPTH + warp) * HDIM);
    const float4* sh4 = reinterpret_cast<const float4*>(sh);

    float acc = 0.0f;
    #pragma unroll
    for (int i = 0; i < HDIM / 128; i++) {   // 4 iterations, 32 lanes x float4
        float4 w = w4[lane + 32 * i];
        float4 h = sh4[lane + 32 * i];
        acc += w.x * h.x + w.y * h.y + w.z * h.z + w.w * h.w;
    }
    #pragma unroll
    for (int o = 16; o; o >>= 1)
        acc += __shfl_xor_sync(0xffffffff, acc, o);
    if (lane == 0) slog[warp] = acc;
    __syncthreads();

    // Warp 0: BCE-with-logits over the 16 path nodes, masked, mean over L
    if (warp == 0) {
        const int L = lengths[word];
        float v = 0.0f;
        if (lane < DPTH) {
            float x = slog[lane];
            float t = codes[(size_t)word * DPTH + lane];
            float bce = fmaxf(x, 0.0f) - x * t + log1pf(expf(-fabsf(x)));
            v = (lane < L) ? bce : 0.0f;
        }
        #pragma unroll
        for (int o = 8; o; o >>= 1)          // lanes 16..31 carry 0, xor-safe
            v += __shfl_xor_sync(0xffffffff, v, o);
        v += __shfl_xor_sync(0xffffffff, v, 16);  // fold upper half (zeros) — no-op but keeps all lanes equal
        if (lane == 0) g_perword[b] = v / (float)L;
    }
}

// Deterministic tree reduction of the 8192 partials -> mean
__global__ __launch_bounds__(1024) void hs_reduce_kernel(float* __restrict__ out)
{
    __shared__ float s[32];
    const int tid = threadIdx.x;
    float acc = 0.0f;
    #pragma unroll
    for (int i = 0; i < BATCH / 1024; i++)
        acc += g_perword[tid + i * 1024];
    #pragma unroll
    for (int o = 16; o; o >>= 1)
        acc += __shfl_xor_sync(0xffffffff, acc, o);
    if ((tid & 31) == 0) s[tid >> 5] = acc;
    __syncthreads();
    if (tid < 32) {
        float v = s[tid];
        #pragma unroll
        for (int o = 16; o; o >>= 1)
            v += __shfl_xor_sync(0xffffffff, v, o);
        if (tid == 0) out[0] = v / (float)BATCH;
    }
}

extern "C" void kernel_launch(void* const* d_in, const int* in_sizes, int n_in,
                              void* d_out, int out_size)
{
    const float* hidden  = (const float*)d_in[0];
    const int*   target  = (const int*)  d_in[1];
    const float* weights = (const float*)d_in[2];
    const float* codes   = (const float*)d_in[3];
    const int*   lengths = (const int*)  d_in[4];
    float* out = (float*)d_out;

    hs_main_kernel<<<BATCH, 512>>>(hidden, target, weights, codes, lengths);
    hs_reduce_kernel<<<1, 1024>>>(out);
}